// round 4
// baseline (speedup 1.0000x reference)
#include <cuda_runtime.h>

typedef unsigned long long ull;

#define NN 50000
#define EE 800000
#define NEG_SLOPE 0.2f
#define LN_EPS 1e-5f

// ---------------- scratch ----------------
__device__ float g_xn[(size_t)NN * 128];
__device__ float g_xl[(size_t)NN * 128];
__device__ float g_xr[(size_t)NN * 128];
__device__ float g_ew[(size_t)EE * 8];
__device__ int g_src[EE], g_dst[EE];
__device__ int g_deg[NN], g_start[NN], g_cursor[NN], g_incl[NN];
__device__ int g_csr[EE];
__device__ int g_bsum[64];
__device__ int g_is64;

// ---------------- packed f32x2 helpers ----------------
__device__ __forceinline__ void ffma2(ull &d, ull a, ull b) {
    asm("fma.rn.f32x2 %0, %1, %2, %0;" : "+l"(d) : "l"(a), "l"(b));
}
__device__ __forceinline__ ull splat2(float x) {
    ull r; asm("mov.b64 %0, {%1, %1};" : "=l"(r) : "f"(x)); return r;
}
__device__ __forceinline__ float2 unpk(ull v) {
    float2 r; asm("mov.b64 {%0, %1}, %2;" : "=f"(r.x), "=f"(r.y) : "l"(v)); return r;
}

// ---------------- edge_index dtype detect + convert ----------------
__global__ void kdetect(const int* p) {
    if (threadIdx.x == 0) {
        int s = 0;
        for (int i = 1; i < 256; i += 2) s |= p[i];
        g_is64 = (s == 0) ? 1 : 0;
    }
}
__global__ void kconvert(const void* ei) {
    int i = blockIdx.x * 256 + threadIdx.x;
    if (i >= EE) return;
    if (g_is64) {
        const long long* p = (const long long*)ei;
        g_src[i] = (int)p[i];
        g_dst[i] = (int)p[EE + i];
    } else {
        const int* p = (const int*)ei;
        g_src[i] = p[i];
        g_dst[i] = p[EE + i];
    }
}

// ---------------- LayerNorm: one warp per node ----------------
__global__ void kln(const float* __restrict__ x, const float* __restrict__ gamma,
                    const float* __restrict__ beta) {
    int w = threadIdx.x >> 5, lane = threadIdx.x & 31;
    int n = blockIdx.x * 8 + w;
    if (n >= NN) return;
    float4 v = *(const float4*)(x + (size_t)n * 128 + lane * 4);
    float s = v.x + v.y + v.z + v.w;
    float sq = v.x * v.x + v.y * v.y + v.z * v.z + v.w * v.w;
#pragma unroll
    for (int o = 16; o > 0; o >>= 1) {
        s += __shfl_xor_sync(0xffffffffu, s, o);
        sq += __shfl_xor_sync(0xffffffffu, sq, o);
    }
    float mean = s * (1.f / 128.f);
    float var = sq * (1.f / 128.f) - mean * mean;
    float inv = rsqrtf(var + LN_EPS);
    float4 g = *(const float4*)(gamma + lane * 4);
    float4 b = *(const float4*)(beta + lane * 4);
    float4 o;
    o.x = (v.x - mean) * inv * g.x + b.x;
    o.y = (v.y - mean) * inv * g.y + b.y;
    o.z = (v.z - mean) * inv * g.z + b.z;
    o.w = (v.w - mean) * inv * g.w + b.w;
    *(float4*)(g_xn + (size_t)n * 128 + lane * 4) = o;
}

// ---------------- shared 64x128 GEMM mainloop (f32x2) ----------------
__device__ __forceinline__ void gemm_tile(const float* __restrict__ A,
                                          const float* __restrict__ B,
                                          long base, long Mlim,
                                          float (*As)[36], float (*Bs)[128],
                                          ull* acc) {
    int tid = threadIdx.x;
    int r0 = (tid >> 4) * 4, c0 = (tid & 15) * 8;
#pragma unroll
    for (int q = 0; q < 16; q++) acc[q] = 0ULL;
    for (int k0 = 0; k0 < 128; k0 += 32) {
        __syncthreads();
#pragma unroll
        for (int t = 0; t < 2; t++) {
            int l = tid + t * 256;
            int row = l >> 3, c4 = (l & 7) * 4;
            long gr = base + row;
            if (gr >= Mlim) gr = Mlim - 1;
            *(float4*)&As[row][c4] = *(const float4*)(A + gr * 128 + k0 + c4);
        }
#pragma unroll
        for (int t = 0; t < 4; t++) {
            int l = tid + t * 256;
            int kr = l >> 5, c4 = (l & 31) * 4;
            *(float4*)&Bs[kr][c4] = *(const float4*)(B + (long)(k0 + kr) * 128 + c4);
        }
        __syncthreads();
#pragma unroll 8
        for (int kk = 0; kk < 32; kk++) {
            ulonglong2 b01 = *(ulonglong2*)&Bs[kk][c0];
            ulonglong2 b23 = *(ulonglong2*)&Bs[kk][c0 + 4];
            ull s0 = splat2(As[r0 + 0][kk]);
            ffma2(acc[0], s0, b01.x);  ffma2(acc[1], s0, b01.y);
            ffma2(acc[2], s0, b23.x);  ffma2(acc[3], s0, b23.y);
            ull s1 = splat2(As[r0 + 1][kk]);
            ffma2(acc[4], s1, b01.x);  ffma2(acc[5], s1, b01.y);
            ffma2(acc[6], s1, b23.x);  ffma2(acc[7], s1, b23.y);
            ull s2 = splat2(As[r0 + 2][kk]);
            ffma2(acc[8], s2, b01.x);  ffma2(acc[9], s2, b01.y);
            ffma2(acc[10], s2, b23.x); ffma2(acc[11], s2, b23.y);
            ull s3 = splat2(As[r0 + 3][kk]);
            ffma2(acc[12], s3, b01.x); ffma2(acc[13], s3, b01.y);
            ffma2(acc[14], s3, b23.x); ffma2(acc[15], s3, b23.y);
        }
    }
}

// ---------------- node GEMMs: xl / xr (select via blockIdx.y) ----------------
__global__ __launch_bounds__(256) void knode(const float* __restrict__ Wl,
                                             const float* __restrict__ bl,
                                             const float* __restrict__ Wr,
                                             const float* __restrict__ br) {
    __shared__ float As[64][36];
    __shared__ float Bs[32][128];
    const float* W = blockIdx.y ? Wr : Wl;
    const float* bv = blockIdx.y ? br : bl;
    float* Co = blockIdx.y ? g_xr : g_xl;
    ull acc[16];
    long base = (long)blockIdx.x * 64;
    gemm_tile(g_xn, W, base, NN, As, Bs, acc);
    int tid = threadIdx.x;
    int r0 = (tid >> 4) * 4, c0 = (tid & 15) * 8;
#pragma unroll
    for (int i = 0; i < 4; i++) {
        long r = base + r0 + i;
        if (r >= NN) break;
#pragma unroll
        for (int j = 0; j < 4; j++) {
            float2 v = unpk(acc[i * 4 + j]);
            int c = c0 + j * 2;
            Co[r * 128 + c] = v.x + bv[c];
            Co[r * 128 + c + 1] = v.y + bv[c + 1];
        }
    }
}

// ---------------- edge GEMM fused with attention score + exp ----------------
__global__ __launch_bounds__(256) void kedge(const float* __restrict__ EA,
                                             const float* __restrict__ We,
                                             const float* __restrict__ be,
                                             const float* __restrict__ att) {
    __shared__ float As[64][36];
    __shared__ float Bs[32][128];
    __shared__ float se[64][8];
    ull acc[16];
    long base = (long)blockIdx.x * 64;
    gemm_tile(EA, We, base, EE, As, Bs, acc);
    int tid = threadIdx.x;
    for (int l = tid; l < 512; l += 256) ((float*)se)[l] = 0.f;
    __syncthreads();
    int r0 = (tid >> 4) * 4, c0 = (tid & 15) * 8, h = c0 >> 4;
    float bev[8], atv[8];
#pragma unroll
    for (int j = 0; j < 8; j++) { bev[j] = be[c0 + j]; atv[j] = att[c0 + j]; }
#pragma unroll
    for (int i = 0; i < 4; i++) {
        long e = base + r0 + i;
        int s = g_src[e], d = g_dst[e];
        const float* xlp = g_xl + (long)s * 128 + c0;
        const float* xrp = g_xr + (long)d * 128 + c0;
        float4 l0 = *(const float4*)xlp, l1 = *(const float4*)(xlp + 4);
        float4 rr0 = *(const float4*)xrp, rr1 = *(const float4*)(xrp + 4);
        float xlv[8] = {l0.x, l0.y, l0.z, l0.w, l1.x, l1.y, l1.z, l1.w};
        float xrv[8] = {rr0.x, rr0.y, rr0.z, rr0.w, rr1.x, rr1.y, rr1.z, rr1.w};
        float m[8];
#pragma unroll
        for (int j = 0; j < 4; j++) {
            float2 v = unpk(acc[i * 4 + j]);
            m[2 * j] = v.x; m[2 * j + 1] = v.y;
        }
        float ps = 0.f;
#pragma unroll
        for (int j = 0; j < 8; j++) {
            float t = m[j] + bev[j] + xlv[j] + xrv[j];
            t = t > 0.f ? t : NEG_SLOPE * t;
            ps += t * atv[j];
        }
        atomicAdd(&se[r0 + i][h], ps);
    }
    __syncthreads();
    for (int l = tid; l < 512; l += 256)
        g_ew[base * 8 + l] = expf(((float*)se)[l]);
}

// ---------------- CSR build ----------------
__global__ void kzero() {
    int i = blockIdx.x * 256 + threadIdx.x;
    if (i < NN) g_deg[i] = 0;
}
__global__ void kdeg() {
    int i = blockIdx.x * 256 + threadIdx.x;
    if (i < EE) atomicAdd(&g_deg[g_dst[i]], 1);
}
__global__ void kscan1() {
    __shared__ int s[1024];
    int tid = threadIdx.x;
    int g = blockIdx.x * 1024 + tid;
    int v = (g < NN) ? g_deg[g] : 0;
    s[tid] = v;
    __syncthreads();
    for (int off = 1; off < 1024; off <<= 1) {
        int t = (tid >= off) ? s[tid - off] : 0;
        __syncthreads();
        s[tid] += t;
        __syncthreads();
    }
    if (g < NN) g_incl[g] = s[tid];
    if (tid == 1023) g_bsum[blockIdx.x] = s[1023];
}
__global__ void kscan2() {
    if (threadIdx.x == 0) {
        int run = 0;
        for (int b = 0; b < 49; b++) { int t = g_bsum[b]; g_bsum[b] = run; run += t; }
    }
}
__global__ void kscan3() {
    int i = blockIdx.x * 256 + threadIdx.x;
    if (i < NN) {
        int st = g_incl[i] - g_deg[i] + g_bsum[i >> 10];
        g_start[i] = st;
        g_cursor[i] = st;
    }
}
__global__ void kfill() {
    int i = blockIdx.x * 256 + threadIdx.x;
    if (i < EE) {
        int p = atomicAdd(&g_cursor[g_dst[i]], 1);
        g_csr[p] = i;
    }
}

// ---------------- aggregation: one warp per node ----------------
__global__ void kagg(const float* __restrict__ bias, float* __restrict__ out) {
    int w = threadIdx.x >> 5, lane = threadIdx.x & 31;
    int n = blockIdx.x * 8 + w;
    if (n >= NN) return;
    int st = g_start[n], de = g_deg[n];
    int h = lane >> 2;
    float ax = 0.f, ay = 0.f, az = 0.f, aw = 0.f, ds = 0.f;
    for (int k = 0; k < de; k++) {
        int e = g_csr[st + k];
        float wg = g_ew[(long)e * 8 + h];
        float4 v = *(const float4*)(g_xl + (long)g_src[e] * 128 + lane * 4);
        ax += wg * v.x; ay += wg * v.y; az += wg * v.z; aw += wg * v.w;
        ds += wg;
    }
    float inv = de ? 1.f / ds : 0.f;
    float4 bv = *(const float4*)(bias + lane * 4);
    float4 o;
    o.x = ax * inv + bv.x;
    o.y = ay * inv + bv.y;
    o.z = az * inv + bv.z;
    o.w = aw * inv + bv.w;
    *(float4*)(out + (long)n * 128 + lane * 4) = o;
}

extern "C" void kernel_launch(void* const* d_in, const int* in_sizes, int n_in,
                              void* d_out, int out_size) {
    const float* x = (const float*)d_in[0];
    const void* ei = d_in[1];
    const float* ea = (const float*)d_in[2];
    const float* gamma = (const float*)d_in[3];
    const float* beta = (const float*)d_in[4];
    const float* Wl = (const float*)d_in[5];
    const float* bl = (const float*)d_in[6];
    const float* Wr = (const float*)d_in[7];
    const float* br = (const float*)d_in[8];
    const float* We = (const float*)d_in[9];
    const float* be = (const float*)d_in[10];
    const float* att = (const float*)d_in[11];
    const float* bias = (const float*)d_in[12];
    float* out = (float*)d_out;

    kdetect<<<1, 1>>>((const int*)ei);
    kconvert<<<3125, 256>>>(ei);
    kln<<<6250, 256>>>(x, gamma, beta);
    dim3 gn(782, 2);
    knode<<<gn, 256>>>(Wl, bl, Wr, br);
    kedge<<<12500, 256>>>(ea, We, be, att);
    kzero<<<196, 256>>>();
    kdeg<<<3125, 256>>>();
    kscan1<<<49, 1024>>>();
    kscan2<<<1, 1>>>();
    kscan3<<<196, 256>>>();
    kfill<<<3125, 256>>>();
    kagg<<<6250, 256>>>(bias, out);
}

// round 8
// speedup vs baseline: 1.4663x; 1.4663x over previous
#include <cuda_runtime.h>
#include <cuda_bf16.h>

typedef unsigned long long ull;
typedef unsigned int u32;

#define NN 50000
#define EE 800000
#define NTILE 6250
#define NEG_SLOPE 0.2f
#define LN_EPS 1e-5f

// ---------------- scratch ----------------
__device__ float g_xn[(size_t)NN * 128];
__device__ float g_xl[(size_t)NN * 128];
__device__ float g_xr[(size_t)NN * 128];
__device__ float g_ew[(size_t)EE * 8];
__device__ int g_src[EE], g_dst[EE];
__device__ int g_deg[NN], g_start[NN], g_cursor[NN], g_incl[NN];
__device__ int g_csr[EE];
__device__ int g_bsum[64];
__device__ int g_is64;
__device__ int g_tile;
// W_e^T bf16 hi/lo images, padded rows: [128][136] bf16 = 34816 B = 2176 uint4
__device__ uint4 g_Bth[2176], g_Btl[2176];

// ---------------- packed f32x2 helpers (SIMT GEMM for knode) ----------------
__device__ __forceinline__ void ffma2(ull &d, ull a, ull b) {
    asm("fma.rn.f32x2 %0, %1, %2, %0;" : "+l"(d) : "l"(a), "l"(b));
}
__device__ __forceinline__ ull splat2(float x) {
    ull r; asm("mov.b64 %0, {%1, %1};" : "=l"(r) : "f"(x)); return r;
}
__device__ __forceinline__ float2 unpk(ull v) {
    float2 r; asm("mov.b64 {%0, %1}, %2;" : "=f"(r.x), "=f"(r.y) : "l"(v)); return r;
}

__device__ __forceinline__ u32 smem_u32(const void* p) {
    u32 a;
    asm("{ .reg .u64 t; cvta.to.shared.u64 t, %1; cvt.u32.u64 %0, t; }" : "=r"(a) : "l"(p));
    return a;
}

// ---------------- edge_index dtype detect + convert (+ tile counter reset) ----------------
__global__ void kdetect(const int* p) {
    if (threadIdx.x == 0) {
        int s = 0;
        for (int i = 1; i < 256; i += 2) s |= p[i];
        g_is64 = (s == 0) ? 1 : 0;
        g_tile = 0;
    }
}
__global__ void kconvert(const void* ei) {
    int i = blockIdx.x * 256 + threadIdx.x;
    if (i >= EE) return;
    if (g_is64) {
        const long long* p = (const long long*)ei;
        g_src[i] = (int)p[i];
        g_dst[i] = (int)p[EE + i];
    } else {
        const int* p = (const int*)ei;
        g_src[i] = p[i];
        g_dst[i] = p[EE + i];
    }
}

// ---------------- LayerNorm: one warp per node ----------------
__global__ void kln(const float* __restrict__ x, const float* __restrict__ gamma,
                    const float* __restrict__ beta) {
    int w = threadIdx.x >> 5, lane = threadIdx.x & 31;
    int n = blockIdx.x * 8 + w;
    if (n >= NN) return;
    float4 v = *(const float4*)(x + (size_t)n * 128 + lane * 4);
    float s = v.x + v.y + v.z + v.w;
    float sq = v.x * v.x + v.y * v.y + v.z * v.z + v.w * v.w;
#pragma unroll
    for (int o = 16; o > 0; o >>= 1) {
        s += __shfl_xor_sync(0xffffffffu, s, o);
        sq += __shfl_xor_sync(0xffffffffu, sq, o);
    }
    float mean = s * (1.f / 128.f);
    float var = sq * (1.f / 128.f) - mean * mean;
    float inv = rsqrtf(var + LN_EPS);
    float4 g = *(const float4*)(gamma + lane * 4);
    float4 b = *(const float4*)(beta + lane * 4);
    float4 o;
    o.x = (v.x - mean) * inv * g.x + b.x;
    o.y = (v.y - mean) * inv * g.y + b.y;
    o.z = (v.z - mean) * inv * g.z + b.z;
    o.w = (v.w - mean) * inv * g.w + b.w;
    *(float4*)(g_xn + (size_t)n * 128 + lane * 4) = o;
}

// ---------------- B prep: W_e^T -> bf16 hi/lo padded images ----------------
__global__ void kprepB(const float* __restrict__ We) {
    int i = blockIdx.x * 256 + threadIdx.x;   // 16384 elements
    int k = i >> 7, n = i & 127;              // We[k][n]; Bt row = n, col = k
    float v = We[i];
    __nv_bfloat16 h = __float2bfloat16(v);
    __nv_bfloat16 l = __float2bfloat16(v - __bfloat162float(h));
    ((__nv_bfloat16*)g_Bth)[n * 136 + k] = h;
    ((__nv_bfloat16*)g_Btl)[n * 136 + k] = l;
}

// ---------------- shared 64x128 SIMT GEMM mainloop (f32x2) for knode ----------------
__device__ __forceinline__ void gemm_tile(const float* __restrict__ A,
                                          const float* __restrict__ B,
                                          long base, long Mlim,
                                          float (*As)[36], float (*Bs)[128],
                                          ull* acc) {
    int tid = threadIdx.x;
    int r0 = (tid >> 4) * 4, c0 = (tid & 15) * 8;
#pragma unroll
    for (int q = 0; q < 16; q++) acc[q] = 0ULL;
    for (int k0 = 0; k0 < 128; k0 += 32) {
        __syncthreads();
#pragma unroll
        for (int t = 0; t < 2; t++) {
            int l = tid + t * 256;
            int row = l >> 3, c4 = (l & 7) * 4;
            long gr = base + row;
            if (gr >= Mlim) gr = Mlim - 1;
            *(float4*)&As[row][c4] = *(const float4*)(A + gr * 128 + k0 + c4);
        }
#pragma unroll
        for (int t = 0; t < 4; t++) {
            int l = tid + t * 256;
            int kr = l >> 5, c4 = (l & 31) * 4;
            *(float4*)&Bs[kr][c4] = *(const float4*)(B + (long)(k0 + kr) * 128 + c4);
        }
        __syncthreads();
#pragma unroll 8
        for (int kk = 0; kk < 32; kk++) {
            ulonglong2 b01 = *(ulonglong2*)&Bs[kk][c0];
            ulonglong2 b23 = *(ulonglong2*)&Bs[kk][c0 + 4];
            ull s0 = splat2(As[r0 + 0][kk]);
            ffma2(acc[0], s0, b01.x);  ffma2(acc[1], s0, b01.y);
            ffma2(acc[2], s0, b23.x);  ffma2(acc[3], s0, b23.y);
            ull s1 = splat2(As[r0 + 1][kk]);
            ffma2(acc[4], s1, b01.x);  ffma2(acc[5], s1, b01.y);
            ffma2(acc[6], s1, b23.x);  ffma2(acc[7], s1, b23.y);
            ull s2 = splat2(As[r0 + 2][kk]);
            ffma2(acc[8], s2, b01.x);  ffma2(acc[9], s2, b01.y);
            ffma2(acc[10], s2, b23.x); ffma2(acc[11], s2, b23.y);
            ull s3 = splat2(As[r0 + 3][kk]);
            ffma2(acc[12], s3, b01.x); ffma2(acc[13], s3, b01.y);
            ffma2(acc[14], s3, b23.x); ffma2(acc[15], s3, b23.y);
        }
    }
}

// ---------------- node GEMMs: xl / xr ----------------
__global__ __launch_bounds__(256) void knode(const float* __restrict__ Wl,
                                             const float* __restrict__ bl,
                                             const float* __restrict__ Wr,
                                             const float* __restrict__ br) {
    __shared__ float As[64][36];
    __shared__ float Bs[32][128];
    const float* W = blockIdx.y ? Wr : Wl;
    const float* bv = blockIdx.y ? br : bl;
    float* Co = blockIdx.y ? g_xr : g_xl;
    ull acc[16];
    long base = (long)blockIdx.x * 64;
    gemm_tile(g_xn, W, base, NN, As, Bs, acc);
    int tid = threadIdx.x;
    int r0 = (tid >> 4) * 4, c0 = (tid & 15) * 8;
#pragma unroll
    for (int i = 0; i < 4; i++) {
        long r = base + r0 + i;
        if (r >= NN) break;
#pragma unroll
        for (int j = 0; j < 4; j++) {
            float2 v = unpk(acc[i * 4 + j]);
            int c = c0 + j * 2;
            Co[r * 128 + c] = v.x + bv[c];
            Co[r * 128 + c + 1] = v.y + bv[c + 1];
        }
    }
}

// ---------------- HMMA edge GEMM (bf16 3-pass split) + fused attention epilogue ----------------
// smem layout (bytes): Ah[128][136]bf16 @0 (34816), Al @34816, Bth @69632, Btl @104448; tot 139264
// C fp32 [128][132] overlays @0 (67584) after mma completes.
#define SM_AH 0
#define SM_AL 34816
#define SM_BH 69632
#define SM_BL 104448
#define SM_TOT 139264

__global__ __launch_bounds__(256, 1) void kedge_m(const float* __restrict__ EA,
                                                  const float* __restrict__ be,
                                                  const float* __restrict__ att) {
    extern __shared__ char sm[];
    __shared__ int s_tile;
    u32 smb = smem_u32(sm);
    int tid = threadIdx.x, wid = tid >> 5, lane = tid & 31;
    int wrow = wid * 16;

    // load B hi/lo images once per CTA
    {
        uint4* dh = (uint4*)(sm + SM_BH);
        uint4* dl = (uint4*)(sm + SM_BL);
        for (int i = tid; i < 2176; i += 256) { dh[i] = g_Bth[i]; dl[i] = g_Btl[i]; }
    }

    // per-lane ldmatrix address offsets (bytes), row stride 272
    u32 a_off = (u32)(wrow + (lane & 7) + ((lane >> 3) & 1) * 8) * 272 + (lane >> 4) * 16;
    u32 b_off = (u32)(lane & 7) * 272 + ((lane >> 3) & 1) * 16;

    for (;;) {
        __syncthreads();                    // prev epilogue done before A overwrite
        if (tid == 0) s_tile = atomicAdd(&g_tile, 1);
        __syncthreads();
        int tile = s_tile;
        if (tile >= NTILE) break;
        long base = (long)tile * 128;

        // ---- load A fp32 [128][128], split to bf16 hi/lo padded tiles ----
#pragma unroll
        for (int t = 0; t < 16; t++) {
            int i4 = tid + t * 256;
            int row = i4 >> 5, c4 = (i4 & 31) << 2;
            float4 v = *(const float4*)(EA + (base + row) * 128 + c4);
            __nv_bfloat16 h0 = __float2bfloat16(v.x), h1 = __float2bfloat16(v.y);
            __nv_bfloat16 h2 = __float2bfloat16(v.z), h3 = __float2bfloat16(v.w);
            __nv_bfloat16 l0 = __float2bfloat16(v.x - __bfloat162float(h0));
            __nv_bfloat16 l1 = __float2bfloat16(v.y - __bfloat162float(h1));
            __nv_bfloat16 l2 = __float2bfloat16(v.z - __bfloat162float(h2));
            __nv_bfloat16 l3 = __float2bfloat16(v.w - __bfloat162float(h3));
            ull ph = (ull)__bfloat16_as_ushort(h0) | ((ull)__bfloat16_as_ushort(h1) << 16)
                   | ((ull)__bfloat16_as_ushort(h2) << 32) | ((ull)__bfloat16_as_ushort(h3) << 48);
            ull pl = (ull)__bfloat16_as_ushort(l0) | ((ull)__bfloat16_as_ushort(l1) << 16)
                   | ((ull)__bfloat16_as_ushort(l2) << 32) | ((ull)__bfloat16_as_ushort(l3) << 48);
            int off = row * 272 + c4 * 2;
            *(ull*)(sm + SM_AH + off) = ph;
            *(ull*)(sm + SM_AL + off) = pl;
        }
        __syncthreads();

        // ---- 3-pass mma: Ah*Bh + Ah*Bl + Al*Bh ----
        float c[16][4];
#pragma unroll
        for (int n = 0; n < 16; n++)
#pragma unroll
            for (int q = 0; q < 4; q++) c[n][q] = 0.f;

#pragma unroll
        for (int p = 0; p < 3; p++) {
            u32 abase = smb + ((p == 2) ? SM_AL : SM_AH) + a_off;
            u32 bbase = smb + ((p == 1) ? SM_BL : SM_BH) + b_off;
#pragma unroll
            for (int k = 0; k < 8; k++) {
                u32 a0, a1, a2, a3;
                asm volatile("ldmatrix.sync.aligned.m8n8.x4.shared.b16 {%0,%1,%2,%3}, [%4];"
                             : "=r"(a0), "=r"(a1), "=r"(a2), "=r"(a3)
                             : "r"(abase + k * 32));
#pragma unroll
                for (int n = 0; n < 16; n++) {
                    u32 b0, b1;
                    asm volatile("ldmatrix.sync.aligned.m8n8.x2.shared.b16 {%0,%1}, [%2];"
                                 : "=r"(b0), "=r"(b1)
                                 : "r"(bbase + n * 2176 + k * 32));
                    asm volatile(
                        "mma.sync.aligned.m16n8k16.row.col.f32.bf16.bf16.f32 "
                        "{%0,%1,%2,%3}, {%4,%5,%6,%7}, {%8,%9}, {%0,%1,%2,%3};"
                        : "+f"(c[n][0]), "+f"(c[n][1]), "+f"(c[n][2]), "+f"(c[n][3])
                        : "r"(a0), "r"(a1), "r"(a2), "r"(a3), "r"(b0), "r"(b1));
                }
            }
        }
        __syncthreads();                    // all mma done before C overlays A

        // ---- spill C to smem fp32 [128][132] ----
        {
            float* Cs = (float*)sm;
            int g = wrow + (lane >> 2), tg = lane & 3;
#pragma unroll
            for (int n = 0; n < 16; n++) {
                *(float2*)(Cs + g * 132 + n * 8 + tg * 2) = make_float2(c[n][0], c[n][1]);
                *(float2*)(Cs + (g + 8) * 132 + n * 8 + tg * 2) = make_float2(c[n][2], c[n][3]);
            }
        }
        __syncthreads();

        // ---- epilogue: 2 threads per edge, 64 cols (4 heads) each ----
        {
            const float* Cs = (const float*)sm;
            int er = tid >> 1, half = tid & 1;
            long e = base + er;
            int s = g_src[e], d = g_dst[e];
            const float* xlp = g_xl + (long)s * 128 + half * 64;
            const float* xrp = g_xr + (long)d * 128 + half * 64;
            const float* mp = Cs + er * 132 + half * 64;
            const float* bep = be + half * 64;
            const float* avp = att + half * 64;
            float sc[4] = {0.f, 0.f, 0.f, 0.f};
#pragma unroll
            for (int j = 0; j < 16; j++) {
                float4 m4 = *(const float4*)(mp + j * 4);
                float4 a4 = *(const float4*)(xlp + j * 4);
                float4 r4 = *(const float4*)(xrp + j * 4);
                float4 bv = *(const float4*)(bep + j * 4);
                float4 av = *(const float4*)(avp + j * 4);
                float t0 = m4.x + bv.x + a4.x + r4.x;
                float t1 = m4.y + bv.y + a4.y + r4.y;
                float t2 = m4.z + bv.z + a4.z + r4.z;
                float t3 = m4.w + bv.w + a4.w + r4.w;
                t0 = t0 > 0.f ? t0 : NEG_SLOPE * t0;
                t1 = t1 > 0.f ? t1 : NEG_SLOPE * t1;
                t2 = t2 > 0.f ? t2 : NEG_SLOPE * t2;
                t3 = t3 > 0.f ? t3 : NEG_SLOPE * t3;
                sc[j >> 2] += t0 * av.x + t1 * av.y + t2 * av.z + t3 * av.w;
            }
            float4 o;
            o.x = expf(sc[0]); o.y = expf(sc[1]);
            o.z = expf(sc[2]); o.w = expf(sc[3]);
            *(float4*)(g_ew + e * 8 + half * 4) = o;
        }
    }
}

// ---------------- CSR build ----------------
__global__ void kzero() {
    int i = blockIdx.x * 256 + threadIdx.x;
    if (i < NN) g_deg[i] = 0;
}
__global__ void kdeg() {
    int i = blockIdx.x * 256 + threadIdx.x;
    if (i < EE) atomicAdd(&g_deg[g_dst[i]], 1);
}
__global__ void kscan1() {
    __shared__ int s[1024];
    int tid = threadIdx.x;
    int g = blockIdx.x * 1024 + tid;
    int v = (g < NN) ? g_deg[g] : 0;
    s[tid] = v;
    __syncthreads();
    for (int off = 1; off < 1024; off <<= 1) {
        int t = (tid >= off) ? s[tid - off] : 0;
        __syncthreads();
        s[tid] += t;
        __syncthreads();
    }
    if (g < NN) g_incl[g] = s[tid];
    if (tid == 1023) g_bsum[blockIdx.x] = s[1023];
}
__global__ void kscan2() {
    if (threadIdx.x == 0) {
        int run = 0;
        for (int b = 0; b < 49; b++) { int t = g_bsum[b]; g_bsum[b] = run; run += t; }
    }
}
__global__ void kscan3() {
    int i = blockIdx.x * 256 + threadIdx.x;
    if (i < NN) {
        int st = g_incl[i] - g_deg[i] + g_bsum[i >> 10];
        g_start[i] = st;
        g_cursor[i] = st;
    }
}
__global__ void kfill() {
    int i = blockIdx.x * 256 + threadIdx.x;
    if (i < EE) {
        int p = atomicAdd(&g_cursor[g_dst[i]], 1);
        g_csr[p] = i;
    }
}

// ---------------- aggregation: one warp per node ----------------
__global__ void kagg(const float* __restrict__ bias, float* __restrict__ out) {
    int w = threadIdx.x >> 5, lane = threadIdx.x & 31;
    int n = blockIdx.x * 8 + w;
    if (n >= NN) return;
    int st = g_start[n], de = g_deg[n];
    int h = lane >> 2;
    float ax = 0.f, ay = 0.f, az = 0.f, aw = 0.f, ds = 0.f;
    for (int k = 0; k < de; k++) {
        int e = g_csr[st + k];
        float wg = g_ew[(long)e * 8 + h];
        float4 v = *(const float4*)(g_xl + (long)g_src[e] * 128 + lane * 4);
        ax += wg * v.x; ay += wg * v.y; az += wg * v.z; aw += wg * v.w;
        ds += wg;
    }
    float inv = de ? 1.f / ds : 0.f;
    float4 bv = *(const float4*)(bias + lane * 4);
    float4 o;
    o.x = ax * inv + bv.x;
    o.y = ay * inv + bv.y;
    o.z = az * inv + bv.z;
    o.w = aw * inv + bv.w;
    *(float4*)(out + (long)n * 128 + lane * 4) = o;
}

extern "C" void kernel_launch(void* const* d_in, const int* in_sizes, int n_in,
                              void* d_out, int out_size) {
    const float* x = (const float*)d_in[0];
    const void* ei = d_in[1];
    const float* ea = (const float*)d_in[2];
    const float* gamma = (const float*)d_in[3];
    const float* beta = (const float*)d_in[4];
    const float* Wl = (const float*)d_in[5];
    const float* bl = (const float*)d_in[6];
    const float* Wr = (const float*)d_in[7];
    const float* br = (const float*)d_in[8];
    const float* We = (const float*)d_in[9];
    const float* be = (const float*)d_in[10];
    const float* att = (const float*)d_in[11];
    const float* bias = (const float*)d_in[12];
    float* out = (float*)d_out;

    static int smem_set = 0;
    if (!smem_set) {
        cudaFuncSetAttribute(kedge_m, cudaFuncAttributeMaxDynamicSharedMemorySize, SM_TOT);
        smem_set = 1;
    }

    kdetect<<<1, 1>>>((const int*)ei);
    kconvert<<<3125, 256>>>(ei);
    kln<<<6250, 256>>>(x, gamma, beta);
    kprepB<<<64, 256>>>(We);
    dim3 gn(782, 2);
    knode<<<gn, 256>>>(Wl, bl, Wr, br);
    kedge_m<<<148, 256, SM_TOT>>>(ea, be, att);
    kzero<<<196, 256>>>();
    kdeg<<<3125, 256>>>();
    kscan1<<<49, 1024>>>();
    kscan2<<<1, 1>>>();
    kscan3<<<196, 256>>>();
    kfill<<<3125, 256>>>();
    kagg<<<6250, 256>>>(bias, out);
}

// round 10
// speedup vs baseline: 1.5326x; 1.0452x over previous
#include <cuda_runtime.h>
#include <cuda_bf16.h>

typedef unsigned long long ull;
typedef unsigned int u32;

#define NN 50000
#define EE 800000
#define NTILE 6250
#define NEG_SLOPE 0.2f
#define LN_EPS 1e-5f

// ---------------- scratch ----------------
__device__ float g_xn[(size_t)NN * 128];
__device__ float g_xl[(size_t)NN * 128];
__device__ float g_xr[(size_t)NN * 128];
__device__ float g_ew[(size_t)EE * 8];
__device__ int g_src[EE], g_dst[EE];
__device__ int g_deg[NN], g_start[NN], g_cursor[NN], g_incl[NN];
__device__ int g_csr[EE];
__device__ int g_bsum[64];
__device__ int g_is64;
__device__ int g_tile;
// bf16 hi/lo weight images, padded rows [128][136] bf16 = 34816 B = 2176 uint4 each
__device__ uint4 g_Bth[2176], g_Btl[2176];          // W_e^T
__device__ uint4 g_Wth[4352], g_Wtl[4352];          // [Wl^T | Wr^T]

__device__ __forceinline__ u32 smem_u32(const void* p) {
    u32 a;
    asm("{ .reg .u64 t; cvta.to.shared.u64 t, %1; cvt.u32.u64 %0, t; }" : "=r"(a) : "l"(p));
    return a;
}

// ---------------- init: zero deg + dtype detect ----------------
__global__ void kdetect(const int* p) {
    int i = blockIdx.x * 256 + threadIdx.x;
    if (i < NN) g_deg[i] = 0;
    if (i == 0) {
        int s = 0;
        for (int j = 1; j < 256; j += 2) s |= p[j];
        g_is64 = (s == 0) ? 1 : 0;
        g_tile = 0;
    }
}
// convert + fused degree histogram
__global__ void kconvert(const void* ei) {
    int i = blockIdx.x * 256 + threadIdx.x;
    if (i >= EE) return;
    int s, d;
    if (g_is64) {
        const long long* p = (const long long*)ei;
        s = (int)p[i];
        d = (int)p[EE + i];
    } else {
        const int* p = (const int*)ei;
        s = p[i];
        d = p[EE + i];
    }
    g_src[i] = s;
    g_dst[i] = d;
    atomicAdd(&g_deg[d], 1);
}

// ---------------- LayerNorm: one warp per node ----------------
__global__ void kln(const float* __restrict__ x, const float* __restrict__ gamma,
                    const float* __restrict__ beta) {
    int w = threadIdx.x >> 5, lane = threadIdx.x & 31;
    int n = blockIdx.x * 8 + w;
    if (n >= NN) return;
    float4 v = *(const float4*)(x + (size_t)n * 128 + lane * 4);
    float s = v.x + v.y + v.z + v.w;
    float sq = v.x * v.x + v.y * v.y + v.z * v.z + v.w * v.w;
#pragma unroll
    for (int o = 16; o > 0; o >>= 1) {
        s += __shfl_xor_sync(0xffffffffu, s, o);
        sq += __shfl_xor_sync(0xffffffffu, sq, o);
    }
    float mean = s * (1.f / 128.f);
    float var = sq * (1.f / 128.f) - mean * mean;
    float inv = rsqrtf(var + LN_EPS);
    float4 g = *(const float4*)(gamma + lane * 4);
    float4 b = *(const float4*)(beta + lane * 4);
    float4 o;
    o.x = (v.x - mean) * inv * g.x + b.x;
    o.y = (v.y - mean) * inv * g.y + b.y;
    o.z = (v.z - mean) * inv * g.z + b.z;
    o.w = (v.w - mean) * inv * g.w + b.w;
    *(float4*)(g_xn + (size_t)n * 128 + lane * 4) = o;
}

// ---------------- weight prep: transpose + bf16 hi/lo split ----------------
__global__ void kprepB(const float* __restrict__ We) {
    int i = blockIdx.x * 256 + threadIdx.x;   // 16384
    int k = i >> 7, n = i & 127;
    float v = We[i];
    __nv_bfloat16 h = __float2bfloat16(v);
    __nv_bfloat16 l = __float2bfloat16(v - __bfloat162float(h));
    ((__nv_bfloat16*)g_Bth)[n * 136 + k] = h;
    ((__nv_bfloat16*)g_Btl)[n * 136 + k] = l;
}
__global__ void kprepW(const float* __restrict__ Wl, const float* __restrict__ Wr) {
    int i = blockIdx.x * 256 + threadIdx.x;   // 32768
    int sel = i >> 14, j = i & 16383;
    int k = j >> 7, n = j & 127;
    float v = sel ? Wr[j] : Wl[j];
    __nv_bfloat16 h = __float2bfloat16(v);
    __nv_bfloat16 l = __float2bfloat16(v - __bfloat162float(h));
    ((__nv_bfloat16*)g_Wth)[sel * 17408 + n * 136 + k] = h;
    ((__nv_bfloat16*)g_Wtl)[sel * 17408 + n * 136 + k] = l;
}

// ---------------- shared HMMA helpers ----------------
// smem layout (bytes): Ah @0, Al @34816, Bh @69632, Bl @104448; total 139264
#define SM_AH 0
#define SM_AL 34816
#define SM_BH 69632
#define SM_BL 104448
#define SM_TOT 139264

// load fp32 tile rows [base..base+127] (clamped to Mlim), split to bf16 hi/lo smem
__device__ __forceinline__ void load_split_A(char* sm, const float* __restrict__ A,
                                             long base, long Mlim, int tid) {
#pragma unroll
    for (int t = 0; t < 16; t++) {
        int i4 = tid + t * 256;
        int row = i4 >> 5, c4 = (i4 & 31) << 2;
        long gr = base + row;
        if (gr >= Mlim) gr = Mlim - 1;
        float4 v = *(const float4*)(A + gr * 128 + c4);
        __nv_bfloat16 h0 = __float2bfloat16(v.x), h1 = __float2bfloat16(v.y);
        __nv_bfloat16 h2 = __float2bfloat16(v.z), h3 = __float2bfloat16(v.w);
        __nv_bfloat16 l0 = __float2bfloat16(v.x - __bfloat162float(h0));
        __nv_bfloat16 l1 = __float2bfloat16(v.y - __bfloat162float(h1));
        __nv_bfloat16 l2 = __float2bfloat16(v.z - __bfloat162float(h2));
        __nv_bfloat16 l3 = __float2bfloat16(v.w - __bfloat162float(h3));
        ull ph = (ull)__bfloat16_as_ushort(h0) | ((ull)__bfloat16_as_ushort(h1) << 16)
               | ((ull)__bfloat16_as_ushort(h2) << 32) | ((ull)__bfloat16_as_ushort(h3) << 48);
        ull pl = (ull)__bfloat16_as_ushort(l0) | ((ull)__bfloat16_as_ushort(l1) << 16)
               | ((ull)__bfloat16_as_ushort(l2) << 32) | ((ull)__bfloat16_as_ushort(l3) << 48);
        int off = row * 272 + c4 * 2;
        *(ull*)(sm + SM_AH + off) = ph;
        *(ull*)(sm + SM_AL + off) = pl;
    }
}

// 3-pass split mainloop: c += Ah*Bh + Ah*Bl + Al*Bh. B ldmatrix.x4 (2 n-atoms/load).
__device__ __forceinline__ void mma_3pass(u32 smb, u32 a_off, u32 b_off, float c[16][4]) {
#pragma unroll
    for (int n = 0; n < 16; n++)
#pragma unroll
        for (int q = 0; q < 4; q++) c[n][q] = 0.f;
#pragma unroll
    for (int p = 0; p < 3; p++) {
        u32 abase = smb + ((p == 2) ? SM_AL : SM_AH) + a_off;
        u32 bbase = smb + ((p == 1) ? SM_BL : SM_BH) + b_off;
#pragma unroll
        for (int k = 0; k < 8; k++) {
            u32 a0, a1, a2, a3;
            asm volatile("ldmatrix.sync.aligned.m8n8.x4.shared.b16 {%0,%1,%2,%3}, [%4];"
                         : "=r"(a0), "=r"(a1), "=r"(a2), "=r"(a3)
                         : "r"(abase + k * 32));
#pragma unroll
            for (int n2 = 0; n2 < 8; n2++) {
                u32 b0, b1, b2, b3;
                asm volatile("ldmatrix.sync.aligned.m8n8.x4.shared.b16 {%0,%1,%2,%3}, [%4];"
                             : "=r"(b0), "=r"(b1), "=r"(b2), "=r"(b3)
                             : "r"(bbase + n2 * 4352 + k * 32));
                asm volatile(
                    "mma.sync.aligned.m16n8k16.row.col.f32.bf16.bf16.f32 "
                    "{%0,%1,%2,%3}, {%4,%5,%6,%7}, {%8,%9}, {%0,%1,%2,%3};"
                    : "+f"(c[2 * n2][0]), "+f"(c[2 * n2][1]), "+f"(c[2 * n2][2]), "+f"(c[2 * n2][3])
                    : "r"(a0), "r"(a1), "r"(a2), "r"(a3), "r"(b0), "r"(b1));
                asm volatile(
                    "mma.sync.aligned.m16n8k16.row.col.f32.bf16.bf16.f32 "
                    "{%0,%1,%2,%3}, {%4,%5,%6,%7}, {%8,%9}, {%0,%1,%2,%3};"
                    : "+f"(c[2 * n2 + 1][0]), "+f"(c[2 * n2 + 1][1]), "+f"(c[2 * n2 + 1][2]), "+f"(c[2 * n2 + 1][3])
                    : "r"(a0), "r"(a1), "r"(a2), "r"(a3), "r"(b2), "r"(b3));
            }
        }
    }
}

// ---------------- HMMA node GEMMs: xl / xr (blockIdx.y selects) ----------------
__global__ __launch_bounds__(256, 1) void knode_m(const float* __restrict__ bl,
                                                  const float* __restrict__ br) {
    extern __shared__ char sm[];
    u32 smb = smem_u32(sm);
    int tid = threadIdx.x, wid = tid >> 5, lane = tid & 31;
    int wrow = wid * 16;
    int sel = blockIdx.y;
    const float* bv = sel ? br : bl;
    float* Co = sel ? g_xr : g_xl;

    // B images for this weight
    {
        uint4* dh = (uint4*)(sm + SM_BH);
        uint4* dl = (uint4*)(sm + SM_BL);
        const uint4* shh = g_Wth + sel * 2176;
        const uint4* sll = g_Wtl + sel * 2176;
        for (int i = tid; i < 2176; i += 256) { dh[i] = shh[i]; dl[i] = sll[i]; }
    }
    long base = (long)blockIdx.x * 128;
    load_split_A(sm, g_xn, base, NN, tid);
    __syncthreads();

    u32 a_off = (u32)(wrow + (lane & 7) + ((lane >> 3) & 1) * 8) * 272 + (lane >> 4) * 16;
    u32 b_off = (u32)(lane & 7) * 272 + ((lane >> 3) & 1) * 16 + (lane >> 4) * 2176;
    float c[16][4];
    mma_3pass(smb, a_off, b_off, c);

    // epilogue: fragments + bias -> global
    long r0g = base + wrow + (lane >> 2);
    long r1g = r0g + 8;
#pragma unroll
    for (int n = 0; n < 16; n++) {
        int col = n * 8 + (lane & 3) * 2;
        float2 bb = *(const float2*)(bv + col);
        if (r0g < NN)
            *(float2*)(Co + r0g * 128 + col) = make_float2(c[n][0] + bb.x, c[n][1] + bb.y);
        if (r1g < NN)
            *(float2*)(Co + r1g * 128 + col) = make_float2(c[n][2] + bb.x, c[n][3] + bb.y);
    }
}

// ---------------- HMMA edge GEMM + fused attention epilogue (persistent) ----------------
__global__ __launch_bounds__(256, 1) void kedge_m(const float* __restrict__ EA,
                                                  const float* __restrict__ be,
                                                  const float* __restrict__ att) {
    extern __shared__ char sm[];
    __shared__ int s_tile;
    u32 smb = smem_u32(sm);
    int tid = threadIdx.x, wid = tid >> 5, lane = tid & 31;
    int wrow = wid * 16;

    {
        uint4* dh = (uint4*)(sm + SM_BH);
        uint4* dl = (uint4*)(sm + SM_BL);
        for (int i = tid; i < 2176; i += 256) { dh[i] = g_Bth[i]; dl[i] = g_Btl[i]; }
    }
    u32 a_off = (u32)(wrow + (lane & 7) + ((lane >> 3) & 1) * 8) * 272 + (lane >> 4) * 16;
    u32 b_off = (u32)(lane & 7) * 272 + ((lane >> 3) & 1) * 16 + (lane >> 4) * 2176;

    for (;;) {
        __syncthreads();                    // prev epilogue done before A overwrite
        if (tid == 0) s_tile = atomicAdd(&g_tile, 1);
        __syncthreads();
        int tile = s_tile;
        if (tile >= NTILE) break;
        long base = (long)tile * 128;

        load_split_A(sm, EA, base, EE, tid);
        __syncthreads();

        float c[16][4];
        mma_3pass(smb, a_off, b_off, c);
        __syncthreads();                    // all mma done before C overlays A

        // spill C to smem fp32 [128][132]
        {
            float* Cs = (float*)sm;
            int g = wrow + (lane >> 2), tg = lane & 3;
#pragma unroll
            for (int n = 0; n < 16; n++) {
                *(float2*)(Cs + g * 132 + n * 8 + tg * 2) = make_float2(c[n][0], c[n][1]);
                *(float2*)(Cs + (g + 8) * 132 + n * 8 + tg * 2) = make_float2(c[n][2], c[n][3]);
            }
        }
        __syncthreads();

        // epilogue: 2 threads per edge, 64 cols (4 heads) each
        {
            const float* Cs = (const float*)sm;
            int er = tid >> 1, half = tid & 1;
            long e = base + er;
            int s = g_src[e], d = g_dst[e];
            const float* xlp = g_xl + (long)s * 128 + half * 64;
            const float* xrp = g_xr + (long)d * 128 + half * 64;
            const float* mp = Cs + er * 132 + half * 64;
            const float* bep = be + half * 64;
            const float* avp = att + half * 64;
            float sc[4] = {0.f, 0.f, 0.f, 0.f};
#pragma unroll
            for (int j = 0; j < 16; j++) {
                float4 m4 = *(const float4*)(mp + j * 4);
                float4 a4 = *(const float4*)(xlp + j * 4);
                float4 r4 = *(const float4*)(xrp + j * 4);
                float4 bb = *(const float4*)(bep + j * 4);
                float4 av = *(const float4*)(avp + j * 4);
                float t0 = m4.x + bb.x + a4.x + r4.x;
                float t1 = m4.y + bb.y + a4.y + r4.y;
                float t2 = m4.z + bb.z + a4.z + r4.z;
                float t3 = m4.w + bb.w + a4.w + r4.w;
                t0 = t0 > 0.f ? t0 : NEG_SLOPE * t0;
                t1 = t1 > 0.f ? t1 : NEG_SLOPE * t1;
                t2 = t2 > 0.f ? t2 : NEG_SLOPE * t2;
                t3 = t3 > 0.f ? t3 : NEG_SLOPE * t3;
                sc[j >> 2] += t0 * av.x + t1 * av.y + t2 * av.z + t3 * av.w;
            }
            float4 o;
            o.x = expf(sc[0]); o.y = expf(sc[1]);
            o.z = expf(sc[2]); o.w = expf(sc[3]);
            *(float4*)(g_ew + e * 8 + half * 4) = o;
        }
    }
}

// ---------------- CSR build ----------------
__global__ void kscan1() {
    __shared__ int s[1024];
    int tid = threadIdx.x;
    int g = blockIdx.x * 1024 + tid;
    int v = (g < NN) ? g_deg[g] : 0;
    s[tid] = v;
    __syncthreads();
    for (int off = 1; off < 1024; off <<= 1) {
        int t = (tid >= off) ? s[tid - off] : 0;
        __syncthreads();
        s[tid] += t;
        __syncthreads();
    }
    if (g < NN) g_incl[g] = s[tid];
    if (tid == 1023) g_bsum[blockIdx.x] = s[1023];
}
__global__ void kscan2() {
    if (threadIdx.x == 0) {
        int run = 0;
        for (int b = 0; b < 49; b++) { int t = g_bsum[b]; g_bsum[b] = run; run += t; }
    }
}
__global__ void kscan3() {
    int i = blockIdx.x * 256 + threadIdx.x;
    if (i < NN) {
        int st = g_incl[i] - g_deg[i] + g_bsum[i >> 10];
        g_start[i] = st;
        g_cursor[i] = st;
    }
}
__global__ void kfill() {
    int i = blockIdx.x * 256 + threadIdx.x;
    if (i < EE) {
        int p = atomicAdd(&g_cursor[g_dst[i]], 1);
        g_csr[p] = i;
    }
}

// ---------------- aggregation: one warp per node ----------------
__global__ void kagg(const float* __restrict__ bias, float* __restrict__ out) {
    int w = threadIdx.x >> 5, lane = threadIdx.x & 31;
    int n = blockIdx.x * 8 + w;
    if (n >= NN) return;
    int st = g_start[n], de = g_deg[n];
    int h = lane >> 2;
    float ax = 0.f, ay = 0.f, az = 0.f, aw = 0.f, ds = 0.f;
    for (int k = 0; k < de; k++) {
        int e = g_csr[st + k];
        float wg = g_ew[(long)e * 8 + h];
        float4 v = *(const float4*)(g_xl + (long)g_src[e] * 128 + lane * 4);
        ax += wg * v.x; ay += wg * v.y; az += wg * v.z; aw += wg * v.w;
        ds += wg;
    }
    float inv = de ? 1.f / ds : 0.f;
    float4 bv = *(const float4*)(bias + lane * 4);
    float4 o;
    o.x = ax * inv + bv.x;
    o.y = ay * inv + bv.y;
    o.z = az * inv + bv.z;
    o.w = aw * inv + bv.w;
    *(float4*)(out + (long)n * 128 + lane * 4) = o;
}

extern "C" void kernel_launch(void* const* d_in, const int* in_sizes, int n_in,
                              void* d_out, int out_size) {
    const float* x = (const float*)d_in[0];
    const void* ei = d_in[1];
    const float* ea = (const float*)d_in[2];
    const float* gamma = (const float*)d_in[3];
    const float* beta = (const float*)d_in[4];
    const float* Wl = (const float*)d_in[5];
    const float* bl = (const float*)d_in[6];
    const float* Wr = (const float*)d_in[7];
    const float* br = (const float*)d_in[8];
    const float* We = (const float*)d_in[9];
    const float* be = (const float*)d_in[10];
    const float* att = (const float*)d_in[11];
    const float* bias = (const float*)d_in[12];
    float* out = (float*)d_out;

    static int smem_set = 0;
    if (!smem_set) {
        cudaFuncSetAttribute(kedge_m, cudaFuncAttributeMaxDynamicSharedMemorySize, SM_TOT);
        cudaFuncSetAttribute(knode_m, cudaFuncAttributeMaxDynamicSharedMemorySize, SM_TOT);
        smem_set = 1;
    }

    kdetect<<<196, 256>>>((const int*)ei);
    kconvert<<<3125, 256>>>(ei);
    kln<<<6250, 256>>>(x, gamma, beta);
    kprepB<<<64, 256>>>(We);
    kprepW<<<128, 256>>>(Wl, Wr);
    dim3 gn(391, 2);
    knode_m<<<gn, 256, SM_TOT>>>(bl, br);
    kedge_m<<<148, 256, SM_TOT>>>(ea, be, att);
    kscan1<<<49, 1024>>>();
    kscan2<<<1, 1>>>();
    kscan3<<<196, 256>>>();
    kfill<<<3125, 256>>>();
    kagg<<<6250, 256>>>(bias, out);
}